// round 12
// baseline (speedup 1.0000x reference)
#include <cuda_runtime.h>

// C[b,g] = softor_s( softand_l( x[b, I[g,s,l]] ) ),  gamma = 1e-3
// B=64, G=2048, S=32, L=8
//
// Scaled domain: w = -x * KINV  (KINV = 1/(gamma*ln2))
//   softand':  mW = max_l w,  sum = sum_l exp2(w_l - mW),  aw = mW + lg2(sum)
//   softor' :  Mw = min_s aw,  S = sum_s exp2(Mw - aw_s)
//              C  = (lg2(S) - Mw) * gamma*ln2
//
// This version stages all 256 gathered rows (64KB) into shared memory with
// cp.async (bulk, latency-amortized), so the hot loop reads LINEAR smem
// addresses: no gather latency, no index indirection, no address ALU.

#define NB 64
#define NG 2048
#define NS 32
#define NL 8
#define NCHUNK 8              // s-dimension split across 8 warps
#define SPER (NS / NCHUNK)    // 4 s-values per chunk
#define NTHR (NCHUNK * 32)    // 256 threads
#define ROWB 256              // bytes per row (64 floats)

#define KINV 1442.6950408889634f
#define GLN2 0.0006931471805599453f

typedef unsigned long long u64;

// Transposed, negated, scaled x: w[g][b] = -x[b][g] * KINV.
__device__ float g_w[NG * NB];

// Tiled transpose 64x2048 -> 2048x64, coalesced both sides; fuses -x*KINV.
__global__ void transpose_kernel(const float* __restrict__ x) {
    __shared__ float tile[32][33];
    const int gx = blockIdx.x * 32;
    const int bx = blockIdx.y * 32;
    const int tx = threadIdx.x;
    const int ty = threadIdx.y;
#pragma unroll
    for (int i = 0; i < 32; i += 8)
        tile[ty + i][tx] = x[(bx + ty + i) * NG + gx + tx] * (-KINV);
    __syncthreads();
#pragma unroll
    for (int i = 0; i < 32; i += 8)
        g_w[(gx + ty + i) * NB + bx + tx] = tile[tx][ty + i];
#if __CUDA_ARCH__ >= 900
    // Trigger AFTER the g_w stores (these must be visible to the dependent
    // grid at its cudaGridDependencySynchronize).
    cudaTriggerProgrammaticLaunchCompletion();
#endif
}

__device__ __forceinline__ float ex2_approx(float t) {
    float r;
    asm("ex2.approx.ftz.f32 %0, %1;" : "=f"(r) : "f"(t));
    return r;
}
__device__ __forceinline__ float lg2_approx(float t) {
    float r;
    asm("lg2.approx.f32 %0, %1;" : "=f"(r) : "f"(t));
    return r;
}

// ---- packed f32x2 helpers (sm_100+: add/sub/mul/fma only) ----
__device__ __forceinline__ u64 fadd2(u64 a, u64 b) {
    u64 r; asm("add.rn.f32x2 %0, %1, %2;" : "=l"(r) : "l"(a), "l"(b)); return r;
}
__device__ __forceinline__ u64 ffma2(u64 a, u64 b, u64 c) {
    u64 r; asm("fma.rn.f32x2 %0, %1, %2, %3;" : "=l"(r) : "l"(a), "l"(b), "l"(c));
    return r;
}
__device__ __forceinline__ void unpack2(u64 t, float& lo, float& hi) {
    asm("mov.b64 {%0, %1}, %2;" : "=f"(lo), "=f"(hi) : "l"(t));
}
__device__ __forceinline__ u64 pack2(float lo, float hi) {
    u64 r; asm("mov.b64 %0, {%1, %2};" : "=l"(r) : "f"(lo), "f"(hi)); return r;
}
__device__ __forceinline__ u64 ex2pair(u64 t) {
    float lo, hi;
    unpack2(t, lo, hi);
    return pack2(ex2_approx(lo), ex2_approx(hi));
}

__device__ __forceinline__ uint smem_u32(const void* p) {
    uint a;
    asm("{ .reg .u64 t; cvta.to.shared.u64 t, %1; cvt.u32.u64 %0, t; }"
        : "=r"(a) : "l"(p));
    return a;
}

// One 256-thread block per g. Dynamic smem: 64KB row buffer.
__global__ __launch_bounds__(NTHR) void clause_kernel(
    const int* __restrict__ I,  // [NG, NS, NL] int32
    float* __restrict__ out)    // [NB, NG]
{
    extern __shared__ float rows[];        // [NS*NL][64] = 64KB

    const int g = blockIdx.x;
    const int tid = threadIdx.x;
    const int lane = tid & 31;
    const int chunk = tid >> 5;

    __shared__ int soff[NS * NL];          // byte offsets into g_w
    __shared__ float2 pM2[NCHUNK][NB / 2];
    __shared__ float2 pS2[NCHUNK][NB / 2];

    // Prologue (independent of g_w — overlaps the transpose under PDL).
    if (tid < NS * NL / 4) {
        int4 r = ((const int4*)(I + g * (NS * NL)))[tid];
        r.x = (r.x & (NG - 1)) << 8;   // row byte offset
        r.y = (r.y & (NG - 1)) << 8;
        r.z = (r.z & (NG - 1)) << 8;
        r.w = (r.w & (NG - 1)) << 8;
        ((int4*)soff)[tid] = r;
    }
    __syncthreads();

#if __CUDA_ARCH__ >= 900
    cudaGridDependencySynchronize();
#endif

    // Bulk prefetch: thread t stages row t (256B) via 16x cp.async.cg.16B.
    {
        const char* src = (const char*)g_w + soff[tid];
        uint dst = smem_u32(rows) + tid * ROWB;
#pragma unroll
        for (int c = 0; c < 16; c++) {
            asm volatile(
                "cp.async.cg.shared.global [%0], [%1], 16;"
                :: "r"(dst + c * 16), "l"(src + c * 16) : "memory");
        }
        asm volatile("cp.async.commit_group;" ::: "memory");
        asm volatile("cp.async.wait_group 0;" ::: "memory");
    }
    __syncthreads();

    // Hot loop: pure LDS + math, linear addressing (rs = s*NL + l).
    const float* lanerow = rows + lane * 2;
    const u64 NEG1x2 = 0xBF800000BF800000ull;  // packed (-1.0f, -1.0f)

    float awx[SPER], awy[SPER];

#pragma unroll
    for (int si = 0; si < SPER; si++) {
        const int s = chunk * SPER + si;
        const float* rbase = lanerow + s * (NL * 64);

        u64 w0 = *(const u64*)(rbase + 0 * 64);
        u64 w1 = *(const u64*)(rbase + 1 * 64);
        u64 w2 = *(const u64*)(rbase + 2 * 64);
        u64 w3 = *(const u64*)(rbase + 3 * 64);
        u64 w4 = *(const u64*)(rbase + 4 * 64);
        u64 w5 = *(const u64*)(rbase + 5 * 64);
        u64 w6 = *(const u64*)(rbase + 6 * 64);
        u64 w7 = *(const u64*)(rbase + 7 * 64);

        float x0, y0, x1, y1, x2, y2, x3, y3;
        float x4, y4, x5, y5, x6, y6, x7, y7;
        unpack2(w0, x0, y0); unpack2(w1, x1, y1);
        unpack2(w2, x2, y2); unpack2(w3, x3, y3);
        unpack2(w4, x4, y4); unpack2(w5, x5, y5);
        unpack2(w6, x6, y6); unpack2(w7, x7, y7);

        float mx = fmaxf(fmaxf(fmaxf(x0, x1), fmaxf(x2, x3)),
                         fmaxf(fmaxf(x4, x5), fmaxf(x6, x7)));
        float my = fmaxf(fmaxf(fmaxf(y0, y1), fmaxf(y2, y3)),
                         fmaxf(fmaxf(y4, y5), fmaxf(y6, y7)));
        u64 m = pack2(mx, my);

        u64 ssum = fadd2(
            fadd2(fadd2(ex2pair(ffma2(m, NEG1x2, w0)),
                        ex2pair(ffma2(m, NEG1x2, w1))),
                  fadd2(ex2pair(ffma2(m, NEG1x2, w2)),
                        ex2pair(ffma2(m, NEG1x2, w3)))),
            fadd2(fadd2(ex2pair(ffma2(m, NEG1x2, w4)),
                        ex2pair(ffma2(m, NEG1x2, w5))),
                  fadd2(ex2pair(ffma2(m, NEG1x2, w6)),
                        ex2pair(ffma2(m, NEG1x2, w7)))));

        float sx, sy;
        unpack2(ssum, sx, sy);
        awx[si] = mx + lg2_approx(sx);
        awy[si] = my + lg2_approx(sy);
    }

    // Partial softor over this chunk's SPER aw values (min in w-domain).
    float Mwx = fminf(fminf(awx[0], awx[1]), fminf(awx[2], awx[3]));
    float Mwy = fminf(fminf(awy[0], awy[1]), fminf(awy[2], awy[3]));
    float Sx = ex2_approx(Mwx - awx[0]) + ex2_approx(Mwx - awx[1])
             + ex2_approx(Mwx - awx[2]) + ex2_approx(Mwx - awx[3]);
    float Sy = ex2_approx(Mwy - awy[0]) + ex2_approx(Mwy - awy[1])
             + ex2_approx(Mwy - awy[2]) + ex2_approx(Mwy - awy[3]);

    pM2[chunk][lane] = make_float2(Mwx, Mwy);
    pS2[chunk][lane] = make_float2(Sx, Sy);
    __syncthreads();

    // First 64 threads: merge NCHUNK partials per b and write out.
    if (tid < NB) {
        const int b = tid;
        const float* pM = (const float*)pM2;  // [NCHUNK][NB]
        const float* pS = (const float*)pS2;
        float Mw = pM[b];
#pragma unroll
        for (int c = 1; c < NCHUNK; c++) Mw = fminf(Mw, pM[c * NB + b]);
        float S = 0.0f;
#pragma unroll
        for (int c = 0; c < NCHUNK; c++)
            S = fmaf(pS[c * NB + b], ex2_approx(Mw - pM[c * NB + b]), S);
        out[b * NG + g] = (lg2_approx(S) - Mw) * GLN2;
    }
}

extern "C" void kernel_launch(void* const* d_in, const int* in_sizes, int n_in,
                              void* d_out, int out_size) {
    // Identify inputs by element count:
    //   x:  64*2048   = 131072 float32
    //   I:  2048*32*8 = 524288 int32
    const float* x = nullptr;
    const int* I = nullptr;
    for (int i = 0; i < n_in; i++) {
        if (in_sizes[i] == NB * NG)           x = (const float*)d_in[i];
        else if (in_sizes[i] == NG * NS * NL) I = (const int*)d_in[i];
    }

    float* out = (float*)d_out;  // [64, 2048] fp32

    const int smem_bytes = NS * NL * ROWB;  // 64KB row buffer
    cudaFuncSetAttribute(clause_kernel,
                         cudaFuncAttributeMaxDynamicSharedMemorySize,
                         smem_bytes);

    dim3 tgrid(NG / 32, NB / 32);
    dim3 tblock(32, 8);
    transpose_kernel<<<tgrid, tblock>>>(x);

    // PDL: clause_kernel launches early; gates on transpose completion
    // (trigger placed after the g_w stores) before touching g_w.
    cudaLaunchConfig_t cfg = {};
    cfg.gridDim = dim3(NG);
    cfg.blockDim = dim3(NTHR);
    cfg.dynamicSmemBytes = smem_bytes;
    cfg.stream = 0;
    cudaLaunchAttribute attr[1];
    attr[0].id = cudaLaunchAttributeProgrammaticStreamSerialization;
    attr[0].val.programmaticStreamSerializationAllowed = 1;
    cfg.attrs = attr;
    cfg.numAttrs = 1;
    cudaLaunchKernelEx(&cfg, clause_kernel, I, (float*)d_out);
}

// round 13
// speedup vs baseline: 2.6271x; 2.6271x over previous
#include <cuda_runtime.h>

// C[b,g] = softor_s( softand_l( x[b, I[g,s,l]] ) ),  gamma = 1e-3
// B=64, G=2048, S=32, L=8
//
// Scaled domain: w = -x * KINV  (KINV = 1/(gamma*ln2))
//   softand':  mW = max_l w,  sum = sum_l exp2(w_l - mW),  aw = mW + lg2(sum)
//   softor' :  Mw = min_s aw,  S = sum_s exp2(Mw - aw_s)
//              C  = (lg2(S) - Mw) * gamma*ln2
//
// R6 scalar body + software-pipelined gathers: iteration si+1's 8 row loads
// are issued before si's compute, keeping 8 LDG.64 in flight behind the
// MUFU chain (gathers are latency-exposed; L1 serves ~60% of them).

#define NB 64
#define NG 2048
#define NS 32
#define NL 8
#define NCHUNK 8              // s-dimension split across 8 warps
#define SPER (NS / NCHUNK)    // 4 s-values per chunk
#define NTHR (NCHUNK * 32)    // 256 threads

#define KINV 1442.6950408889634f
#define GLN2 0.0006931471805599453f

// Transposed, negated, scaled x: w[g][b] = -x[b][g] * KINV.
__device__ float g_w[NG * NB];

// Tiled transpose 64x2048 -> 2048x64, coalesced both sides; fuses -x*KINV.
__global__ void transpose_kernel(const float* __restrict__ x) {
    __shared__ float tile[32][33];
    const int gx = blockIdx.x * 32;
    const int bx = blockIdx.y * 32;
    const int tx = threadIdx.x;
    const int ty = threadIdx.y;
#pragma unroll
    for (int i = 0; i < 32; i += 8)
        tile[ty + i][tx] = x[(bx + ty + i) * NG + gx + tx] * (-KINV);
    __syncthreads();
#pragma unroll
    for (int i = 0; i < 32; i += 8)
        g_w[(gx + ty + i) * NB + bx + tx] = tile[tx][ty + i];
#if __CUDA_ARCH__ >= 900
    // Trigger AFTER the g_w stores (these must be visible to the dependent
    // grid at its cudaGridDependencySynchronize).
    cudaTriggerProgrammaticLaunchCompletion();
#endif
}

__device__ __forceinline__ float ex2_approx(float t) {
    float r;
    asm("ex2.approx.ftz.f32 %0, %1;" : "=f"(r) : "f"(t));
    return r;
}
__device__ __forceinline__ float lg2_approx(float t) {
    float r;
    asm("lg2.approx.f32 %0, %1;" : "=f"(r) : "f"(t));
    return r;
}

// One block (256 threads) per g; regs allowed to float for load pipelining.
__global__ __launch_bounds__(NTHR) void clause_kernel(
    const int* __restrict__ I,  // [NG, NS, NL] int32
    float* __restrict__ out)    // [NB, NG]
{
    const int g = blockIdx.x;
    const int tid = threadIdx.x;
    const int lane = tid & 31;
    const int chunk = tid >> 5;

    __shared__ int soff[NS * NL];          // pre-shifted byte offsets
    __shared__ float2 pM2[NCHUNK][NB / 2]; // partial min(aw) per chunk
    __shared__ float2 pS2[NCHUNK][NB / 2]; // partial sum-of-exp per chunk

    // Prologue: independent of g_w — overlaps with the transpose under PDL.
    if (tid < NS * NL / 4) {
        int4 r = ((const int4*)(I + g * (NS * NL)))[tid];
        r.x = (r.x & (NG - 1)) << 8;   // *256 bytes = row stride in bytes
        r.y = (r.y & (NG - 1)) << 8;
        r.z = (r.z & (NG - 1)) << 8;
        r.w = (r.w & (NG - 1)) << 8;
        ((int4*)soff)[tid] = r;
    }
    __syncthreads();

#if __CUDA_ARCH__ >= 900
    cudaGridDependencySynchronize();
#endif

    const char* lanebase = (const char*)g_w + lane * sizeof(float2);
    const int4* __restrict__ soff4 = (const int4*)(soff + chunk * SPER * NL);

    float awx[SPER], awy[SPER];

    // Pipelined gather loop: prefetch si+1's 8 rows before computing si.
    int4 oA = soff4[0];
    int4 oB = soff4[1];
    float2 w0 = *(const float2*)(lanebase + oA.x);
    float2 w1 = *(const float2*)(lanebase + oA.y);
    float2 w2 = *(const float2*)(lanebase + oA.z);
    float2 w3 = *(const float2*)(lanebase + oA.w);
    float2 w4 = *(const float2*)(lanebase + oB.x);
    float2 w5 = *(const float2*)(lanebase + oB.y);
    float2 w6 = *(const float2*)(lanebase + oB.z);
    float2 w7 = *(const float2*)(lanebase + oB.w);

#pragma unroll
    for (int si = 0; si < SPER; si++) {
        float2 n0, n1, n2, n3, n4, n5, n6, n7;
        if (si + 1 < SPER) {
            const int4 nA = soff4[(si + 1) * 2 + 0];
            const int4 nB = soff4[(si + 1) * 2 + 1];
            n0 = *(const float2*)(lanebase + nA.x);
            n1 = *(const float2*)(lanebase + nA.y);
            n2 = *(const float2*)(lanebase + nA.z);
            n3 = *(const float2*)(lanebase + nA.w);
            n4 = *(const float2*)(lanebase + nB.x);
            n5 = *(const float2*)(lanebase + nB.y);
            n6 = *(const float2*)(lanebase + nB.z);
            n7 = *(const float2*)(lanebase + nB.w);
        }

        float mx = fmaxf(fmaxf(fmaxf(w0.x, w1.x), fmaxf(w2.x, w3.x)),
                         fmaxf(fmaxf(w4.x, w5.x), fmaxf(w6.x, w7.x)));
        float my = fmaxf(fmaxf(fmaxf(w0.y, w1.y), fmaxf(w2.y, w3.y)),
                         fmaxf(fmaxf(w4.y, w5.y), fmaxf(w6.y, w7.y)));

        float sx = ex2_approx(w0.x - mx) + ex2_approx(w1.x - mx)
                 + ex2_approx(w2.x - mx) + ex2_approx(w3.x - mx)
                 + ex2_approx(w4.x - mx) + ex2_approx(w5.x - mx)
                 + ex2_approx(w6.x - mx) + ex2_approx(w7.x - mx);
        float sy = ex2_approx(w0.y - my) + ex2_approx(w1.y - my)
                 + ex2_approx(w2.y - my) + ex2_approx(w3.y - my)
                 + ex2_approx(w4.y - my) + ex2_approx(w5.y - my)
                 + ex2_approx(w6.y - my) + ex2_approx(w7.y - my);

        awx[si] = mx + lg2_approx(sx);
        awy[si] = my + lg2_approx(sy);

        if (si + 1 < SPER) {
            w0 = n0; w1 = n1; w2 = n2; w3 = n3;
            w4 = n4; w5 = n5; w6 = n6; w7 = n7;
        }
    }

    // Partial softor over this chunk's SPER aw values (min in w-domain).
    float Mwx = fminf(fminf(awx[0], awx[1]), fminf(awx[2], awx[3]));
    float Mwy = fminf(fminf(awy[0], awy[1]), fminf(awy[2], awy[3]));
    float Sx = ex2_approx(Mwx - awx[0]) + ex2_approx(Mwx - awx[1])
             + ex2_approx(Mwx - awx[2]) + ex2_approx(Mwx - awx[3]);
    float Sy = ex2_approx(Mwy - awy[0]) + ex2_approx(Mwy - awy[1])
             + ex2_approx(Mwy - awy[2]) + ex2_approx(Mwy - awy[3]);

    pM2[chunk][lane] = make_float2(Mwx, Mwy);
    pS2[chunk][lane] = make_float2(Sx, Sy);
    __syncthreads();

    // First 64 threads: merge NCHUNK partials per b and write out.
    if (tid < NB) {
        const int b = tid;
        const float* pM = (const float*)pM2;  // [NCHUNK][NB]
        const float* pS = (const float*)pS2;
        float Mw = pM[b];
#pragma unroll
        for (int c = 1; c < NCHUNK; c++) Mw = fminf(Mw, pM[c * NB + b]);
        float S = 0.0f;
#pragma unroll
        for (int c = 0; c < NCHUNK; c++)
            S = fmaf(pS[c * NB + b], ex2_approx(Mw - pM[c * NB + b]), S);
        out[b * NG + g] = (lg2_approx(S) - Mw) * GLN2;
    }
}

extern "C" void kernel_launch(void* const* d_in, const int* in_sizes, int n_in,
                              void* d_out, int out_size) {
    // Identify inputs by element count:
    //   x:  64*2048   = 131072 float32
    //   I:  2048*32*8 = 524288 int32
    const float* x = nullptr;
    const int* I = nullptr;
    for (int i = 0; i < n_in; i++) {
        if (in_sizes[i] == NB * NG)           x = (const float*)d_in[i];
        else if (in_sizes[i] == NG * NS * NL) I = (const int*)d_in[i];
    }

    float* out = (float*)d_out;  // [64, 2048] fp32

    dim3 tgrid(NG / 32, NB / 32);
    dim3 tblock(32, 8);
    transpose_kernel<<<tgrid, tblock>>>(x);

    // PDL: clause_kernel launches early; gates on transpose completion
    // (trigger placed after the g_w stores) before touching g_w.
    cudaLaunchConfig_t cfg = {};
    cfg.gridDim = dim3(NG);
    cfg.blockDim = dim3(NTHR);
    cfg.dynamicSmemBytes = 0;
    cfg.stream = 0;
    cudaLaunchAttribute attr[1];
    attr[0].id = cudaLaunchAttributeProgrammaticStreamSerialization;
    attr[0].val.programmaticStreamSerializationAllowed = 1;
    cfg.attrs = attr;
    cfg.numAttrs = 1;
    cudaLaunchKernelEx(&cfg, clause_kernel, I, (float*)d_out);
}